// round 1
// baseline (speedup 1.0000x reference)
#include <cuda_runtime.h>

#define B 32
#define K 1024
#define F 128
#define E 128
#define OUT2 125
#define ALPHA 0.2f

#define TILE_I 16
#define JC 64
#define KCH 32

// Scratch (device globals: allocation-free)
__device__ float g_w1[F];
__device__ float g_w2[F];
__device__ float g_c[2];
__device__ float g_s1[B * K];
__device__ float g_s2[B * K];
__device__ float g_h[(size_t)B * K * F];        // 16 MB
__device__ float g_h2[(size_t)B * F * OUT2];    // 2 MB

// ---------------------------------------------------------------------------
// k1: fold attention vector a into per-feature weights.
// w1[f] = sum_e lin_w[e,f] * a1[e];  c1 = lin_b . a1   (same for 2)
// ---------------------------------------------------------------------------
__global__ void k1_prep(const float* __restrict__ lin_w,
                        const float* __restrict__ lin_b,
                        const float* __restrict__ a) {
    int f = threadIdx.x;  // 0..127
    __shared__ float sa1[E], sa2[E], red1[E], red2[E];
    float a1v = a[f], a2v = a[E + f];
    sa1[f] = a1v;
    sa2[f] = a2v;
    __syncthreads();
    float acc1 = 0.f, acc2 = 0.f;
#pragma unroll 8
    for (int e = 0; e < E; e++) {
        float lw = lin_w[e * F + f];
        acc1 += lw * sa1[e];
        acc2 += lw * sa2[e];
    }
    g_w1[f] = acc1;
    g_w2[f] = acc2;
    float lb = lin_b[f];
    red1[f] = lb * a1v;
    red2[f] = lb * a2v;
    __syncthreads();
    for (int s = 64; s > 0; s >>= 1) {
        if (f < s) {
            red1[f] += red1[f + s];
            red2[f] += red2[f + s];
        }
        __syncthreads();
    }
    if (f == 0) {
        g_c[0] = red1[0];
        g_c[1] = red2[0];
    }
}

// ---------------------------------------------------------------------------
// k2: s1[b,k] = x[b,k,:].w1 + c1 ; s2 likewise. One warp per row.
// ---------------------------------------------------------------------------
__global__ void k2_scores(const float* __restrict__ x) {
    int row = (blockIdx.x * blockDim.x + threadIdx.x) >> 5;
    int lane = threadIdx.x & 31;
    if (row >= B * K) return;
    float4 xv = ((const float4*)(x + (size_t)row * F))[lane];
    float4 w1 = ((const float4*)g_w1)[lane];
    float4 w2 = ((const float4*)g_w2)[lane];
    float d1 = xv.x * w1.x + xv.y * w1.y + xv.z * w1.z + xv.w * w1.w;
    float d2 = xv.x * w2.x + xv.y * w2.y + xv.z * w2.z + xv.w * w2.w;
#pragma unroll
    for (int off = 16; off; off >>= 1) {
        d1 += __shfl_xor_sync(~0u, d1, off);
        d2 += __shfl_xor_sync(~0u, d2, off);
    }
    if (lane == 0) {
        g_s1[row] = d1 + g_c[0];
        g_s2[row] = d2 + g_c[1];
    }
}

// ---------------------------------------------------------------------------
// k3: per (b, 16-row i tile):
//   Phase A: e = leaky(s1_i + s2_j) + bias_ij -> softmax row -> write attn,
//            keep normalized P in smem.
//   Phase B: h[i,:] = P[i,:] @ x[b] + x[b,i,:]  (register-tiled)
// dyn smem: P (16*1024f) + s2 (1024f) + x chunk (64*128f) = 100 KB
// ---------------------------------------------------------------------------
__global__ void __launch_bounds__(256, 2)
k3_attn(const float* __restrict__ x, const float* __restrict__ bias,
        float* __restrict__ attn_out) {
    extern __shared__ float smem[];
    float* p_s  = smem;                   // TILE_I * K
    float* s2_s = p_s + TILE_I * K;       // K
    float* x_s  = s2_s + K;               // JC * F

    int b = blockIdx.y;
    int i0g = blockIdx.x * TILE_I;
    int tid = threadIdx.x;
    int warp = tid >> 5, lane = tid & 31;

    for (int j = tid; j < K; j += 256) s2_s[j] = g_s2[b * K + j];
    __syncthreads();

    // ---- Phase A: 8 warps x 2 rows each ----
#pragma unroll
    for (int r = 0; r < 2; r++) {
        int i = warp * 2 + r;
        int gi = i0g + i;
        float s1 = g_s1[b * K + gi];
        const float* brow = bias + (size_t)gi * K;
        float m = -1e30f;
        for (int j = lane; j < K; j += 32) {
            float v = s1 + s2_s[j];
            v = v > 0.f ? v : ALPHA * v;
            v += brow[j];
            p_s[i * K + j] = v;
            m = fmaxf(m, v);
        }
#pragma unroll
        for (int off = 16; off; off >>= 1)
            m = fmaxf(m, __shfl_xor_sync(~0u, m, off));
        float sum = 0.f;
        for (int j = lane; j < K; j += 32) {
            float pv = __expf(p_s[i * K + j] - m);
            p_s[i * K + j] = pv;
            sum += pv;
        }
#pragma unroll
        for (int off = 16; off; off >>= 1)
            sum += __shfl_xor_sync(~0u, sum, off);
        float inv = 1.0f / sum;
        float* arow = attn_out + ((size_t)(b * K + gi)) * K;
        for (int j = lane; j < K; j += 32) {
            float pv = p_s[i * K + j] * inv;
            p_s[i * K + j] = pv;
            arow[j] = pv;
        }
    }
    __syncthreads();

    // ---- Phase B: h = P @ x + x ----
    int f4 = tid & 31;   // float4 column
    int rq = tid >> 5;   // 0..7
    int i0 = rq, i1 = rq + 8;
    const float* xb = x + (size_t)b * K * F;
    float4 acc0 = ((const float4*)(xb + (size_t)(i0g + i0) * F))[f4];
    float4 acc1 = ((const float4*)(xb + (size_t)(i0g + i1) * F))[f4];

    for (int jc = 0; jc < K; jc += JC) {
        __syncthreads();
        const float4* src = (const float4*)(xb + (size_t)jc * F);
        float4* dst = (float4*)x_s;
        for (int l = tid; l < JC * F / 4; l += 256) dst[l] = src[l];
        __syncthreads();
#pragma unroll 8
        for (int jj = 0; jj < JC; jj++) {
            float4 xv = ((const float4*)x_s)[jj * 32 + f4];
            float pa = p_s[i0 * K + jc + jj];
            float pb = p_s[i1 * K + jc + jj];
            acc0.x += pa * xv.x; acc0.y += pa * xv.y;
            acc0.z += pa * xv.z; acc0.w += pa * xv.w;
            acc1.x += pb * xv.x; acc1.y += pb * xv.y;
            acc1.z += pb * xv.z; acc1.w += pb * xv.w;
        }
    }
    float4* hout = (float4*)(g_h + (size_t)b * K * F);
    hout[(i0g + i0) * 32 + f4] = acc0;
    hout[(i0g + i1) * 32 + f4] = acc1;
}

// ---------------------------------------------------------------------------
// k4: h2[b,f,o] += sum_k h[b,k,f]*lin2_w[o,k]  (k split across blockIdx.y)
// 8x8 register tile per thread, smem-staged chunks, atomic accumulation.
// ---------------------------------------------------------------------------
__global__ void __launch_bounds__(256)
k4_lin2(const float* __restrict__ lin2_w) {
    __shared__ __align__(16) float hs[KCH][F];    // 16 KB
    __shared__ __align__(16) float ws[KCH][132];  // 16.5 KB (o padded)
    int b = blockIdx.x;
    int k0 = blockIdx.y * 256;
    int tid = threadIdx.x;
    int f0 = (tid & 15) * 8;
    int o0 = (tid >> 4) * 8;
    float acc[8][8];
#pragma unroll
    for (int i = 0; i < 8; i++)
#pragma unroll
        for (int j = 0; j < 8; j++) acc[i][j] = 0.f;

    for (int kc = k0; kc < k0 + 256; kc += KCH) {
        __syncthreads();
        const float4* hsrc = (const float4*)(g_h + ((size_t)b * K + kc) * F);
        for (int l = tid; l < KCH * F / 4; l += 256) ((float4*)hs)[l] = hsrc[l];
        for (int l = tid; l < OUT2 * KCH; l += 256) {
            int o = l / KCH, kk = l % KCH;
            ws[kk][o] = lin2_w[(size_t)o * K + kc + kk];
        }
        // zero padded o columns once per chunk
        for (int l = tid; l < (132 - OUT2) * KCH; l += 256) {
            int o = OUT2 + l / KCH, kk = l % KCH;
            ws[kk][o] = 0.f;
        }
        __syncthreads();
#pragma unroll 4
        for (int kk = 0; kk < KCH; kk++) {
            float hv[8], wv[8];
            float4 h0 = *(const float4*)&hs[kk][f0];
            float4 h1 = *(const float4*)&hs[kk][f0 + 4];
            hv[0] = h0.x; hv[1] = h0.y; hv[2] = h0.z; hv[3] = h0.w;
            hv[4] = h1.x; hv[5] = h1.y; hv[6] = h1.z; hv[7] = h1.w;
            float4 w0 = *(const float4*)&ws[kk][o0];
            float4 w1 = *(const float4*)&ws[kk][o0 + 4];
            wv[0] = w0.x; wv[1] = w0.y; wv[2] = w0.z; wv[3] = w0.w;
            wv[4] = w1.x; wv[5] = w1.y; wv[6] = w1.z; wv[7] = w1.w;
#pragma unroll
            for (int i = 0; i < 8; i++)
#pragma unroll
                for (int j = 0; j < 8; j++) acc[i][j] += hv[i] * wv[j];
        }
    }
#pragma unroll
    for (int i = 0; i < 8; i++)
#pragma unroll
        for (int j = 0; j < 8; j++) {
            int o = o0 + j;
            if (o < OUT2)
                atomicAdd(&g_h2[((size_t)b * F + f0 + i) * OUT2 + o], acc[i][j]);
        }
}

// ---------------------------------------------------------------------------
// k5: out_h2 = relu(g_h2 + lin2_b)
// ---------------------------------------------------------------------------
__global__ void k5_out(const float* __restrict__ lin2_b, float* __restrict__ out) {
    int i = blockIdx.x * 256 + threadIdx.x;
    if (i >= B * F * OUT2) return;
    int o = i % OUT2;
    float v = g_h2[i] + lin2_b[o];
    out[i] = v > 0.f ? v : 0.f;
}

// ---------------------------------------------------------------------------
extern "C" void kernel_launch(void* const* d_in, const int* in_sizes, int n_in,
                              void* d_out, int out_size) {
    const float* x      = (const float*)d_in[0];
    const float* lin_w  = (const float*)d_in[1];
    const float* lin_b  = (const float*)d_in[2];
    const float* a      = (const float*)d_in[3];
    const float* bias   = (const float*)d_in[4];
    const float* lin2_w = (const float*)d_in[5];
    const float* lin2_b = (const float*)d_in[6];
    float* out = (float*)d_out;
    float* out_h2 = out;                              // (B,F,OUT2)
    float* out_attn = out + (size_t)B * F * OUT2;     // (B,K,K)

    const int SMEM3 = (TILE_I * K + K + JC * F) * (int)sizeof(float);  // 100 KB
    cudaFuncSetAttribute(k3_attn, cudaFuncAttributeMaxDynamicSharedMemorySize, SMEM3);

    void* h2ptr = nullptr;
    cudaGetSymbolAddress(&h2ptr, g_h2);
    cudaMemsetAsync(h2ptr, 0, sizeof(float) * B * F * OUT2);

    k1_prep<<<1, 128>>>(lin_w, lin_b, a);
    k2_scores<<<(B * K) / 8, 256>>>(x);
    k3_attn<<<dim3(K / TILE_I, B), 256, SMEM3>>>(x, bias, out_attn);
    k4_lin2<<<dim3(B, 4), 256>>>(lin2_w);
    k5_out<<<(B * F * OUT2 + 255) / 256, 256>>>(lin2_b, out_h2);
}

// round 3
// speedup vs baseline: 2.5428x; 2.5428x over previous
#include <cuda_runtime.h>
#include <cstdint>

#define B 32
#define K 1024
#define F 128
#define E 128
#define OUT2 125
#define ALPHA 0.2f

#define KCH 32      // k4 k-chunk
#define PPITCH 36   // P tile smem pitch (floats): (row*4+col)%32 distinct for 8x4 frag
#define XPITCH 136  // X tile smem pitch (floats): (j*8+f)%32 distinct for 4x8 frag

// -------------------- scratch (device globals, allocation-free) ------------
__device__ float g_w1[F];
__device__ float g_w2[F];
__device__ float g_c[2];
__device__ float g_s1[B * K];
__device__ float g_s2[B * K];
__device__ float g_h[(size_t)B * K * F];           // 16 MB
__device__ float g_h2p[16][(size_t)B * F * OUT2];  // 32.8 MB partials

__device__ __forceinline__ uint32_t f2tf32(float v) {
    uint32_t o;
    asm("cvt.rna.tf32.f32 %0, %1;" : "=r"(o) : "f"(v));
    return o;
}

// ---------------------------------------------------------------------------
// k1: fold a into per-feature weights: w1 = lin_w^T a1, c1 = lin_b.a1 (and 2)
// ---------------------------------------------------------------------------
__global__ void k1_prep(const float* __restrict__ lin_w,
                        const float* __restrict__ lin_b,
                        const float* __restrict__ a) {
    int f = threadIdx.x;
    __shared__ float sa1[E], sa2[E], red1[E], red2[E];
    float a1v = a[f], a2v = a[E + f];
    sa1[f] = a1v;
    sa2[f] = a2v;
    __syncthreads();
    float acc1 = 0.f, acc2 = 0.f;
#pragma unroll 8
    for (int e = 0; e < E; e++) {
        float lw = lin_w[e * F + f];
        acc1 += lw * sa1[e];
        acc2 += lw * sa2[e];
    }
    g_w1[f] = acc1;
    g_w2[f] = acc2;
    float lb = lin_b[f];
    red1[f] = lb * a1v;
    red2[f] = lb * a2v;
    __syncthreads();
    for (int s = 64; s > 0; s >>= 1) {
        if (f < s) {
            red1[f] += red1[f + s];
            red2[f] += red2[f + s];
        }
        __syncthreads();
    }
    if (f == 0) {
        g_c[0] = red1[0];
        g_c[1] = red2[0];
    }
}

// ---------------------------------------------------------------------------
// k2: s1/s2 row scores. One warp per row.
// ---------------------------------------------------------------------------
__global__ void k2_scores(const float* __restrict__ x) {
    int row = (blockIdx.x * blockDim.x + threadIdx.x) >> 5;
    int lane = threadIdx.x & 31;
    if (row >= B * K) return;
    float4 xv = ((const float4*)(x + (size_t)row * F))[lane];
    float4 w1 = ((const float4*)g_w1)[lane];
    float4 w2 = ((const float4*)g_w2)[lane];
    float d1 = xv.x * w1.x + xv.y * w1.y + xv.z * w1.z + xv.w * w1.w;
    float d2 = xv.x * w2.x + xv.y * w2.y + xv.z * w2.z + xv.w * w2.w;
#pragma unroll
    for (int off = 16; off; off >>= 1) {
        d1 += __shfl_xor_sync(~0u, d1, off);
        d2 += __shfl_xor_sync(~0u, d2, off);
    }
    if (lane == 0) {
        g_s1[row] = d1 + g_c[0];
        g_s2[row] = d2 + g_c[1];
    }
}

// ---------------------------------------------------------------------------
// k3a: softmax rows, register-resident. One warp per row (8 rows / block).
// ---------------------------------------------------------------------------
__global__ void __launch_bounds__(256) k3a_softmax(const float* __restrict__ bias,
                                                   float* __restrict__ attn) {
    __shared__ float s2s[K];
    int b = blockIdx.y;
    int tid = threadIdx.x, warp = tid >> 5, lane = tid & 31;
    for (int j = tid; j < K; j += 256) s2s[j] = g_s2[b * K + j];
    __syncthreads();
    int gi = blockIdx.x * 8 + warp;
    float s1 = g_s1[b * K + gi];
    const float* brow = bias + (size_t)gi * K;
    float ev[32];
    float m = -1e30f;
#pragma unroll
    for (int t = 0; t < 32; t++) {
        int j = lane + t * 32;
        float v = s1 + s2s[j];
        v = v > 0.f ? v : ALPHA * v;
        v += brow[j];
        ev[t] = v;
        m = fmaxf(m, v);
    }
#pragma unroll
    for (int off = 16; off; off >>= 1) m = fmaxf(m, __shfl_xor_sync(~0u, m, off));
    float sum = 0.f;
#pragma unroll
    for (int t = 0; t < 32; t++) {
        ev[t] = __expf(ev[t] - m);
        sum += ev[t];
    }
#pragma unroll
    for (int off = 16; off; off >>= 1) sum += __shfl_xor_sync(~0u, sum, off);
    float inv = 1.0f / sum;
    float* arow = attn + ((size_t)(b * K + gi)) * K;
#pragma unroll
    for (int t = 0; t < 32; t++) arow[lane + t * 32] = ev[t] * inv;
}

// ---------------------------------------------------------------------------
// k3b: h = P @ x + x via mma.sync.m16n8k8 tf32.
// Block: 256 thr = 8 warps (2 m x 4 n). Block tile M=128 (i), N=128 (f).
// Warp tile 64x32. K staged in 32-wide chunks:
//   Ps[128][36]  : P rows (i), k contiguous
//   Xs[32][136]  : x rows (j=k), f contiguous (B operand read as [k][n])
// ---------------------------------------------------------------------------
__global__ void __launch_bounds__(256) k3b_gemm(const float* __restrict__ x,
                                                const float* __restrict__ attn) {
    __shared__ __align__(16) uint32_t Ps[128 * PPITCH];
    __shared__ __align__(16) uint32_t Xs[32 * XPITCH];

    const int tid = threadIdx.x;
    const int wid = tid >> 5, lane = tid & 31;
    const int b = blockIdx.y;
    const int i0 = blockIdx.x * 128;
    const int warp_m = (wid >> 2) * 64;  // 0 or 64
    const int warp_n = (wid & 3) * 32;   // 0..96
    const int qr = lane >> 2;            // quad row 0..7
    const int qc = lane & 3;             // quad col 0..3

    const float* Pg = attn + ((size_t)b * K + i0) * K;
    const float* Xb = x + (size_t)b * K * F;

    float acc[4][4][4];
#pragma unroll
    for (int mt = 0; mt < 4; mt++)
#pragma unroll
        for (int nt = 0; nt < 4; nt++)
#pragma unroll
            for (int q = 0; q < 4; q++) acc[mt][nt][q] = 0.f;

    for (int jc = 0; jc < K; jc += 32) {
        __syncthreads();
        // stage P tile (128 rows x 32 k), cvt to tf32
#pragma unroll
        for (int t = 0; t < 4; t++) {
            int idx = tid + t * 256;
            int row = idx >> 3, c4 = idx & 7;
            float4 v = *(const float4*)(Pg + (size_t)row * K + jc + c4 * 4);
            uint32_t* dst = Ps + row * PPITCH + c4 * 4;
            dst[0] = f2tf32(v.x);
            dst[1] = f2tf32(v.y);
            dst[2] = f2tf32(v.z);
            dst[3] = f2tf32(v.w);
        }
        // stage X tile (32 j-rows x 128 f), cvt to tf32
#pragma unroll
        for (int t = 0; t < 4; t++) {
            int idx = tid + t * 256;
            int jj = idx >> 5, f4 = idx & 31;
            float4 v = *(const float4*)(Xb + (size_t)(jc + jj) * F + f4 * 4);
            uint32_t* dst = Xs + jj * XPITCH + f4 * 4;
            dst[0] = f2tf32(v.x);
            dst[1] = f2tf32(v.y);
            dst[2] = f2tf32(v.z);
            dst[3] = f2tf32(v.w);
        }
        __syncthreads();

#pragma unroll
        for (int kk = 0; kk < 4; kk++) {
            // A fragments: 4 m-tiles x 4 regs
            uint32_t af[4][4];
#pragma unroll
            for (int mt = 0; mt < 4; mt++) {
                const uint32_t* base = Ps + (warp_m + mt * 16 + qr) * PPITCH + kk * 8 + qc;
                af[mt][0] = base[0];
                af[mt][1] = base[8 * PPITCH];
                af[mt][2] = base[4];
                af[mt][3] = base[8 * PPITCH + 4];
            }
            // B fragments: 4 n-tiles x 2 regs  (B[k][n] from Xs[j][f])
            uint32_t bf[4][2];
#pragma unroll
            for (int nt = 0; nt < 4; nt++) {
                const uint32_t* base = Xs + (kk * 8 + qc) * XPITCH + warp_n + nt * 8 + qr;
                bf[nt][0] = base[0];
                bf[nt][1] = base[4 * XPITCH];
            }
#pragma unroll
            for (int mt = 0; mt < 4; mt++)
#pragma unroll
                for (int nt = 0; nt < 4; nt++) {
                    asm volatile(
                        "mma.sync.aligned.m16n8k8.row.col.f32.tf32.tf32.f32 "
                        "{%0,%1,%2,%3}, {%4,%5,%6,%7}, {%8,%9}, {%0,%1,%2,%3};"
                        : "+f"(acc[mt][nt][0]), "+f"(acc[mt][nt][1]),
                          "+f"(acc[mt][nt][2]), "+f"(acc[mt][nt][3])
                        : "r"(af[mt][0]), "r"(af[mt][1]), "r"(af[mt][2]), "r"(af[mt][3]),
                          "r"(bf[nt][0]), "r"(bf[nt][1]));
                }
        }
    }

    // epilogue: h = acc + x
#pragma unroll
    for (int mt = 0; mt < 4; mt++) {
        int r0 = i0 + warp_m + mt * 16 + qr;
#pragma unroll
        for (int nt = 0; nt < 4; nt++) {
            int fc = warp_n + nt * 8 + qc * 2;
            float2 xv0 = *(const float2*)(Xb + (size_t)r0 * F + fc);
            float2 xv1 = *(const float2*)(Xb + (size_t)(r0 + 8) * F + fc);
            float2 o0 = {acc[mt][nt][0] + xv0.x, acc[mt][nt][1] + xv0.y};
            float2 o1 = {acc[mt][nt][2] + xv1.x, acc[mt][nt][3] + xv1.y};
            *(float2*)(g_h + ((size_t)b * K + r0) * F + fc) = o0;
            *(float2*)(g_h + ((size_t)b * K + r0 + 8) * F + fc) = o1;
        }
    }
}

// ---------------------------------------------------------------------------
// k4: partial h2[b,f,o] over 64-k range per block, atomic-free partials.
// ---------------------------------------------------------------------------
__global__ void __launch_bounds__(256) k4_lin2(const float* __restrict__ lin2_w) {
    __shared__ __align__(16) float hs[KCH][F];
    __shared__ __align__(16) float ws[KCH][132];
    int b = blockIdx.x;
    int ksplit = blockIdx.y;
    int k0 = ksplit * 64;
    int tid = threadIdx.x;
    int f0 = (tid & 15) * 8;
    int o0 = (tid >> 4) * 8;
    float acc[8][8];
#pragma unroll
    for (int i = 0; i < 8; i++)
#pragma unroll
        for (int j = 0; j < 8; j++) acc[i][j] = 0.f;

    for (int kc = k0; kc < k0 + 64; kc += KCH) {
        __syncthreads();
        const float4* hsrc = (const float4*)(g_h + ((size_t)b * K + kc) * F);
        for (int l = tid; l < KCH * F / 4; l += 256) ((float4*)hs)[l] = hsrc[l];
        for (int l = tid; l < OUT2 * KCH; l += 256) {
            int o = l / KCH, kk = l % KCH;
            ws[kk][o] = lin2_w[(size_t)o * K + kc + kk];
        }
        for (int l = tid; l < (132 - OUT2) * KCH; l += 256) {
            int o = OUT2 + l / KCH, kk = l % KCH;
            ws[kk][o] = 0.f;
        }
        __syncthreads();
#pragma unroll 4
        for (int kk = 0; kk < KCH; kk++) {
            float hv[8], wv[8];
            float4 h0 = *(const float4*)&hs[kk][f0];
            float4 h1 = *(const float4*)&hs[kk][f0 + 4];
            hv[0] = h0.x; hv[1] = h0.y; hv[2] = h0.z; hv[3] = h0.w;
            hv[4] = h1.x; hv[5] = h1.y; hv[6] = h1.z; hv[7] = h1.w;
            float4 w0 = *(const float4*)&ws[kk][o0];
            float4 w1 = *(const float4*)&ws[kk][o0 + 4];
            wv[0] = w0.x; wv[1] = w0.y; wv[2] = w0.z; wv[3] = w0.w;
            wv[4] = w1.x; wv[5] = w1.y; wv[6] = w1.z; wv[7] = w1.w;
#pragma unroll
            for (int i = 0; i < 8; i++)
#pragma unroll
                for (int j = 0; j < 8; j++) acc[i][j] += hv[i] * wv[j];
        }
    }
#pragma unroll
    for (int i = 0; i < 8; i++)
#pragma unroll
        for (int j = 0; j < 8; j++) {
            int o = o0 + j;
            if (o < OUT2)
                g_h2p[ksplit][((size_t)b * F + f0 + i) * OUT2 + o] = acc[i][j];
        }
}

// ---------------------------------------------------------------------------
// k5: out = relu(sum partials + lin2_b)
// ---------------------------------------------------------------------------
__global__ void k5_out(const float* __restrict__ lin2_b, float* __restrict__ out) {
    int i = blockIdx.x * 256 + threadIdx.x;
    if (i >= B * F * OUT2) return;
    float v = lin2_b[i % OUT2];
#pragma unroll
    for (int p = 0; p < 16; p++) v += g_h2p[p][i];
    out[i] = v > 0.f ? v : 0.f;
}

// ---------------------------------------------------------------------------
extern "C" void kernel_launch(void* const* d_in, const int* in_sizes, int n_in,
                              void* d_out, int out_size) {
    const float* x      = (const float*)d_in[0];
    const float* lin_w  = (const float*)d_in[1];
    const float* lin_b  = (const float*)d_in[2];
    const float* a      = (const float*)d_in[3];
    const float* bias   = (const float*)d_in[4];
    const float* lin2_w = (const float*)d_in[5];
    const float* lin2_b = (const float*)d_in[6];
    float* out = (float*)d_out;
    float* out_h2 = out;                           // (B,F,OUT2)
    float* out_attn = out + (size_t)B * F * OUT2;  // (B,K,K)

    k1_prep<<<1, 128>>>(lin_w, lin_b, a);
    k2_scores<<<(B * K) / 8, 256>>>(x);
    k3a_softmax<<<dim3(K / 8, B), 256>>>(bias, out_attn);
    k3b_gemm<<<dim3(K / 128, B), 256>>>(x, out_attn);
    k4_lin2<<<dim3(B, 16), 256>>>(lin2_w);
    k5_out<<<(B * F * OUT2 + 255) / 256, 256>>>(lin2_b, out_h2);
}

// round 4
// speedup vs baseline: 2.5972x; 1.0214x over previous
#include <cuda_runtime.h>
#include <cstdint>

#define B 32
#define K 1024
#define F 128
#define E 128
#define OUT2 125
#define ALPHA 0.2f

#define NCH3 32              // k3b chunks (K/32)
#define PPITCHF 36           // A-tile pitch in floats (144 B, 16B aligned)
#define XPITCHF 136          // B-tile pitch in floats (544 B, 16B aligned)
#define PBUF 18432           // 128*36*4
#define XBUF 17408           // 32*136*4
#define SMEM_GEMM 71680      // 2*(PBUF+XBUF)
#define NSPLIT 4             // k4 k-splits

// -------------------- scratch (device globals, allocation-free) ------------
__device__ float g_w1[F];
__device__ float g_w2[F];
__device__ float g_c[2];
__device__ float g_s1[B * K];
__device__ float g_s2[B * K];
__device__ float g_h[(size_t)B * K * F];               // 16 MB
__device__ float g_h2p[NSPLIT][(size_t)B * F * OUT2];  // 8.2 MB partials

__device__ __forceinline__ uint32_t smem_u32(const void* p) {
    uint32_t a;
    asm("{ .reg .u64 t; cvta.to.shared.u64 t, %1; cvt.u32.u64 %0, t; }" : "=r"(a) : "l"(p));
    return a;
}
__device__ __forceinline__ void cp16(uint32_t dst, const void* src) {
    asm volatile("cp.async.cg.shared.global [%0], [%1], 16;" :: "r"(dst), "l"(src) : "memory");
}
__device__ __forceinline__ void cp16z(uint32_t dst, const void* src, int bytes) {
    asm volatile("cp.async.cg.shared.global [%0], [%1], 16, %2;"
                 :: "r"(dst), "l"(src), "r"(bytes) : "memory");
}
__device__ __forceinline__ void cp_commit() {
    asm volatile("cp.async.commit_group;" ::: "memory");
}
#define CP_WAIT(n) asm volatile("cp.async.wait_group %0;" :: "n"(n) : "memory")

#define MMA_TF32(acc, af, bf)                                              \
    asm volatile(                                                          \
        "mma.sync.aligned.m16n8k8.row.col.f32.tf32.tf32.f32 "              \
        "{%0,%1,%2,%3}, {%4,%5,%6,%7}, {%8,%9}, {%0,%1,%2,%3};"            \
        : "+f"((acc)[0]), "+f"((acc)[1]), "+f"((acc)[2]), "+f"((acc)[3])   \
        : "r"((af)[0]), "r"((af)[1]), "r"((af)[2]), "r"((af)[3]),          \
          "r"((bf)[0]), "r"((bf)[1]))

// ---------------------------------------------------------------------------
// k1: fold a into per-feature weights: w1 = lin_w^T a1, c1 = lin_b.a1 (and 2)
// ---------------------------------------------------------------------------
__global__ void k1_prep(const float* __restrict__ lin_w,
                        const float* __restrict__ lin_b,
                        const float* __restrict__ a) {
    int f = threadIdx.x;
    __shared__ float sa1[E], sa2[E], red1[E], red2[E];
    float a1v = a[f], a2v = a[E + f];
    sa1[f] = a1v;
    sa2[f] = a2v;
    __syncthreads();
    float acc1 = 0.f, acc2 = 0.f;
#pragma unroll 8
    for (int e = 0; e < E; e++) {
        float lw = lin_w[e * F + f];
        acc1 += lw * sa1[e];
        acc2 += lw * sa2[e];
    }
    g_w1[f] = acc1;
    g_w2[f] = acc2;
    float lb = lin_b[f];
    red1[f] = lb * a1v;
    red2[f] = lb * a2v;
    __syncthreads();
    for (int s = 64; s > 0; s >>= 1) {
        if (f < s) {
            red1[f] += red1[f + s];
            red2[f] += red2[f + s];
        }
        __syncthreads();
    }
    if (f == 0) {
        g_c[0] = red1[0];
        g_c[1] = red2[0];
    }
}

// ---------------------------------------------------------------------------
// k2: s1/s2 row scores. One warp per row.
// ---------------------------------------------------------------------------
__global__ void k2_scores(const float* __restrict__ x) {
    int row = (blockIdx.x * blockDim.x + threadIdx.x) >> 5;
    int lane = threadIdx.x & 31;
    if (row >= B * K) return;
    float4 xv = ((const float4*)(x + (size_t)row * F))[lane];
    float4 w1 = ((const float4*)g_w1)[lane];
    float4 w2 = ((const float4*)g_w2)[lane];
    float d1 = xv.x * w1.x + xv.y * w1.y + xv.z * w1.z + xv.w * w1.w;
    float d2 = xv.x * w2.x + xv.y * w2.y + xv.z * w2.z + xv.w * w2.w;
#pragma unroll
    for (int off = 16; off; off >>= 1) {
        d1 += __shfl_xor_sync(~0u, d1, off);
        d2 += __shfl_xor_sync(~0u, d2, off);
    }
    if (lane == 0) {
        g_s1[row] = d1 + g_c[0];
        g_s2[row] = d2 + g_c[1];
    }
}

// ---------------------------------------------------------------------------
// k3a: softmax rows, register-resident. One warp per row (8 rows / block).
// ---------------------------------------------------------------------------
__global__ void __launch_bounds__(256) k3a_softmax(const float* __restrict__ bias,
                                                   float* __restrict__ attn) {
    __shared__ float s2s[K];
    int b = blockIdx.y;
    int tid = threadIdx.x, warp = tid >> 5, lane = tid & 31;
    for (int j = tid; j < K; j += 256) s2s[j] = g_s2[b * K + j];
    __syncthreads();
    int gi = blockIdx.x * 8 + warp;
    float s1 = g_s1[b * K + gi];
    const float* brow = bias + (size_t)gi * K;
    float ev[32];
    float m = -1e30f;
#pragma unroll
    for (int t = 0; t < 32; t++) {
        int j = lane + t * 32;
        float v = s1 + s2s[j];
        v = v > 0.f ? v : ALPHA * v;
        v += brow[j];
        ev[t] = v;
        m = fmaxf(m, v);
    }
#pragma unroll
    for (int off = 16; off; off >>= 1) m = fmaxf(m, __shfl_xor_sync(~0u, m, off));
    float sum = 0.f;
#pragma unroll
    for (int t = 0; t < 32; t++) {
        ev[t] = __expf(ev[t] - m);
        sum += ev[t];
    }
#pragma unroll
    for (int off = 16; off; off >>= 1) sum += __shfl_xor_sync(~0u, sum, off);
    float inv = 1.0f / sum;
    float* arow = attn + ((size_t)(b * K + gi)) * K;
#pragma unroll
    for (int t = 0; t < 32; t++) arow[lane + t * 32] = ev[t] * inv;
}

// ---------------------------------------------------------------------------
// k3b: h = P @ x + x via mma.sync tf32, cp.async double-buffered.
// Raw fp32 bits fed as tf32 (HW truncates). Block 256 thr = 8 warps (2m x 4n).
// smem: A(P) [128 x 32] pitch 36f  x2 | B(x) [32 x 128] pitch 136f  x2
// ---------------------------------------------------------------------------
__global__ void __launch_bounds__(256, 2) k3b_gemm(const float* __restrict__ x,
                                                   const float* __restrict__ attn) {
    extern __shared__ char sm[];
    const uint32_t sbase = smem_u32(sm);
    const int tid = threadIdx.x;
    const int wid = tid >> 5, lane = tid & 31;
    const int b = blockIdx.y;
    const int i0 = blockIdx.x * 128;
    const int warp_m = (wid >> 2) * 64;
    const int warp_n = (wid & 3) * 32;
    const int qr = lane >> 2, qc = lane & 3;

    const float* Pg = attn + ((size_t)b * K + i0) * K;
    const float* Xb = x + (size_t)b * K * F;

    const int r8 = tid >> 3, c8 = tid & 7;    // P staging coords (row, float4 col)
    const int j32 = tid >> 5, f32 = tid & 31; // X staging coords

    float acc[4][4][4];
#pragma unroll
    for (int mt = 0; mt < 4; mt++)
#pragma unroll
        for (int nt = 0; nt < 4; nt++)
#pragma unroll
            for (int q = 0; q < 4; q++) acc[mt][nt][q] = 0.f;

#define STAGE3(c, bi)                                                              \
    do {                                                                           \
        uint32_t pd = sbase + (bi) * PBUF;                                         \
        uint32_t xd = sbase + 2 * PBUF + (bi) * XBUF;                              \
        _Pragma("unroll") for (int t = 0; t < 4; t++) {                            \
            int row = r8 + t * 32;                                                 \
            cp16(pd + row * 144 + c8 * 16, Pg + (size_t)row * K + (c) * 32 + c8 * 4); \
        }                                                                          \
        _Pragma("unroll") for (int t = 0; t < 4; t++) {                            \
            int jj = j32 + t * 8;                                                  \
            cp16(xd + jj * 544 + f32 * 16, Xb + (size_t)((c) * 32 + jj) * F + f32 * 4); \
        }                                                                          \
        cp_commit();                                                               \
    } while (0)

    STAGE3(0, 0);
    for (int c = 0; c < NCH3; c++) {
        int bi = c & 1;
        if (c + 1 < NCH3) {
            STAGE3(c + 1, bi ^ 1);
            CP_WAIT(1);
        } else {
            CP_WAIT(0);
        }
        __syncthreads();
        const uint32_t* Ps = (const uint32_t*)(sm + bi * PBUF);
        const uint32_t* Xs = (const uint32_t*)(sm + 2 * PBUF + bi * XBUF);
#pragma unroll
        for (int kk = 0; kk < 4; kk++) {
            uint32_t af[4][4];
#pragma unroll
            for (int mt = 0; mt < 4; mt++) {
                const uint32_t* base = Ps + (warp_m + mt * 16 + qr) * PPITCHF + kk * 8 + qc;
                af[mt][0] = base[0];
                af[mt][1] = base[8 * PPITCHF];
                af[mt][2] = base[4];
                af[mt][3] = base[8 * PPITCHF + 4];
            }
            uint32_t bf[4][2];
#pragma unroll
            for (int nt = 0; nt < 4; nt++) {
                const uint32_t* base = Xs + (kk * 8 + qc) * XPITCHF + warp_n + nt * 8 + qr;
                bf[nt][0] = base[0];
                bf[nt][1] = base[4 * XPITCHF];
            }
#pragma unroll
            for (int mt = 0; mt < 4; mt++)
#pragma unroll
                for (int nt = 0; nt < 4; nt++) MMA_TF32(acc[mt][nt], af[mt], bf[nt]);
        }
        __syncthreads();
    }

    // epilogue: h = acc + x
#pragma unroll
    for (int mt = 0; mt < 4; mt++) {
        int r0 = i0 + warp_m + mt * 16 + qr;
#pragma unroll
        for (int nt = 0; nt < 4; nt++) {
            int fc = warp_n + nt * 8 + qc * 2;
            float2 xv0 = *(const float2*)(Xb + (size_t)r0 * F + fc);
            float2 xv1 = *(const float2*)(Xb + (size_t)(r0 + 8) * F + fc);
            float2 o0 = {acc[mt][nt][0] + xv0.x, acc[mt][nt][1] + xv0.y};
            float2 o1 = {acc[mt][nt][2] + xv1.x, acc[mt][nt][3] + xv1.y};
            *(float2*)(g_h + ((size_t)b * K + r0) * F + fc) = o0;
            *(float2*)(g_h + ((size_t)b * K + r0 + 8) * F + fc) = o1;
        }
    }
}

// ---------------------------------------------------------------------------
// k4: h2 partial via tensor mma. A = lin2_w [o x k] (row-major), B = h [k x f].
// D[o][f] -> g_h2p[split][b][f][o]. grid (B, NSPLIT), k-range 256 per block.
// ---------------------------------------------------------------------------
__global__ void __launch_bounds__(256, 2) k4_lin2(const float* __restrict__ lin2_w) {
    extern __shared__ char sm[];
    const uint32_t sbase = smem_u32(sm);
    const int tid = threadIdx.x;
    const int wid = tid >> 5, lane = tid & 31;
    const int b = blockIdx.x;
    const int ks = blockIdx.y;
    const int k0 = ks * (K / NSPLIT);
    const int warp_m = (wid >> 2) * 64;
    const int warp_n = (wid & 3) * 32;
    const int qr = lane >> 2, qc = lane & 3;

    const float* Hb = g_h + (size_t)b * K * F;

    const int r8 = tid >> 3, c8 = tid & 7;
    const int j32 = tid >> 5, f32 = tid & 31;

    float acc[4][4][4];
#pragma unroll
    for (int mt = 0; mt < 4; mt++)
#pragma unroll
        for (int nt = 0; nt < 4; nt++)
#pragma unroll
            for (int q = 0; q < 4; q++) acc[mt][nt][q] = 0.f;

#define STAGE4(c, bi)                                                                   \
    do {                                                                                \
        uint32_t ad = sbase + (bi) * PBUF;                                              \
        uint32_t bd = sbase + 2 * PBUF + (bi) * XBUF;                                   \
        _Pragma("unroll") for (int t = 0; t < 4; t++) {                                 \
            int row = r8 + t * 32;                                                      \
            int vb = row < OUT2 ? 16 : 0;                                               \
            cp16z(ad + row * 144 + c8 * 16,                                             \
                  lin2_w + (size_t)(row < OUT2 ? row : 0) * K + k0 + (c) * 32 + c8 * 4, \
                  vb);                                                                  \
        }                                                                               \
        _Pragma("unroll") for (int t = 0; t < 4; t++) {                                 \
            int jj = j32 + t * 8;                                                       \
            cp16(bd + jj * 544 + f32 * 16,                                              \
                 Hb + (size_t)(k0 + (c) * 32 + jj) * F + f32 * 4);                      \
        }                                                                               \
        cp_commit();                                                                    \
    } while (0)

    const int NCH4 = (K / NSPLIT) / 32;  // 8
    STAGE4(0, 0);
    for (int c = 0; c < NCH4; c++) {
        int bi = c & 1;
        if (c + 1 < NCH4) {
            STAGE4(c + 1, bi ^ 1);
            CP_WAIT(1);
        } else {
            CP_WAIT(0);
        }
        __syncthreads();
        const uint32_t* As = (const uint32_t*)(sm + bi * PBUF);
        const uint32_t* Bs = (const uint32_t*)(sm + 2 * PBUF + bi * XBUF);
#pragma unroll
        for (int kk = 0; kk < 4; kk++) {
            uint32_t af[4][4];
#pragma unroll
            for (int mt = 0; mt < 4; mt++) {
                const uint32_t* base = As + (warp_m + mt * 16 + qr) * PPITCHF + kk * 8 + qc;
                af[mt][0] = base[0];
                af[mt][1] = base[8 * PPITCHF];
                af[mt][2] = base[4];
                af[mt][3] = base[8 * PPITCHF + 4];
            }
            uint32_t bf[4][2];
#pragma unroll
            for (int nt = 0; nt < 4; nt++) {
                const uint32_t* base = Bs + (kk * 8 + qc) * XPITCHF + warp_n + nt * 8 + qr;
                bf[nt][0] = base[0];
                bf[nt][1] = base[4 * XPITCHF];
            }
#pragma unroll
            for (int mt = 0; mt < 4; mt++)
#pragma unroll
                for (int nt = 0; nt < 4; nt++) MMA_TF32(acc[mt][nt], af[mt], bf[nt]);
        }
        __syncthreads();
    }

    // epilogue: D[o][f] -> partial [b][f][o]
    float* out = g_h2p[ks] + (size_t)b * F * OUT2;
#pragma unroll
    for (int mt = 0; mt < 4; mt++) {
        int o0 = warp_m + mt * 16 + qr;
#pragma unroll
        for (int nt = 0; nt < 4; nt++) {
            int fc = warp_n + nt * 8 + qc * 2;
            if (o0 < OUT2) {
                out[(size_t)fc * OUT2 + o0] = acc[mt][nt][0];
                out[(size_t)(fc + 1) * OUT2 + o0] = acc[mt][nt][1];
            }
            if (o0 + 8 < OUT2) {
                out[(size_t)fc * OUT2 + o0 + 8] = acc[mt][nt][2];
                out[(size_t)(fc + 1) * OUT2 + o0 + 8] = acc[mt][nt][3];
            }
        }
    }
}

// ---------------------------------------------------------------------------
// k5: out = relu(sum partials + lin2_b)
// ---------------------------------------------------------------------------
__global__ void k5_out(const float* __restrict__ lin2_b, float* __restrict__ out) {
    int i = blockIdx.x * 256 + threadIdx.x;
    if (i >= B * F * OUT2) return;
    float v = lin2_b[i % OUT2];
#pragma unroll
    for (int p = 0; p < NSPLIT; p++) v += g_h2p[p][i];
    out[i] = v > 0.f ? v : 0.f;
}

// ---------------------------------------------------------------------------
extern "C" void kernel_launch(void* const* d_in, const int* in_sizes, int n_in,
                              void* d_out, int out_size) {
    const float* x      = (const float*)d_in[0];
    const float* lin_w  = (const float*)d_in[1];
    const float* lin_b  = (const float*)d_in[2];
    const float* a      = (const float*)d_in[3];
    const float* bias   = (const float*)d_in[4];
    const float* lin2_w = (const float*)d_in[5];
    const float* lin2_b = (const float*)d_in[6];
    float* out = (float*)d_out;
    float* out_h2 = out;                           // (B,F,OUT2)
    float* out_attn = out + (size_t)B * F * OUT2;  // (B,K,K)

    cudaFuncSetAttribute(k3b_gemm, cudaFuncAttributeMaxDynamicSharedMemorySize, SMEM_GEMM);
    cudaFuncSetAttribute(k4_lin2, cudaFuncAttributeMaxDynamicSharedMemorySize, SMEM_GEMM);

    k1_prep<<<1, 128>>>(lin_w, lin_b, a);
    k2_scores<<<(B * K) / 8, 256>>>(x);
    k3a_softmax<<<dim3(K / 8, B), 256>>>(bias, out_attn);
    k3b_gemm<<<dim3(K / 128, B), 256, SMEM_GEMM>>>(x, out_attn);
    k4_lin2<<<dim3(B, NSPLIT), 256, SMEM_GEMM>>>(lin2_w);
    k5_out<<<(B * F * OUT2 + 255) / 256, 256>>>(lin2_b, out_h2);
}

// round 5
// speedup vs baseline: 3.1621x; 1.2175x over previous
#include <cuda_runtime.h>
#include <cstdint>

#define B 32
#define K 1024
#define F 128
#define E 128
#define OUT2 125
#define ALPHA 0.2f

#define PPITCHF 36           // A-tile pitch (floats)
#define XPITCHF 136          // B-tile pitch (floats)
#define PBUF 18432           // 128*36*4 bytes
#define XBUF 17408           // 32*136*4 bytes
#define NSPLIT 4             // k4 k-splits

// k3f dynamic smem offsets (bytes)
#define OFF_S2  0
#define OFF_S1  4096
#define OFF_INV 4608
#define OFF_P   5120
#define OFF_X   (OFF_P + 2 * PBUF)          // 41984
#define SMEM_K3F (OFF_X + 2 * XBUF)         // 76800
#define SMEM_K4 (2 * (PBUF + XBUF))         // 71680

// -------------------- scratch (device globals, allocation-free) ------------
__device__ float g_w1[F];
__device__ float g_w2[F];
__device__ float g_c[2];
__device__ float g_s1[B * K];
__device__ float g_s2[B * K];
__device__ float g_xr[(size_t)B * K * F];              // tf32-rounded x
__device__ float g_wr[OUT2 * K];                       // tf32-rounded lin2_w
__device__ float g_h[(size_t)B * K * F];               // h (tf32-rounded values)
__device__ float g_h2p[NSPLIT][(size_t)B * F * OUT2];  // partials

__device__ __forceinline__ uint32_t smem_u32(const void* p) {
    uint32_t a;
    asm("{ .reg .u64 t; cvta.to.shared.u64 t, %1; cvt.u32.u64 %0, t; }" : "=r"(a) : "l"(p));
    return a;
}
__device__ __forceinline__ float f2tf32f(float v) {
    uint32_t o;
    asm("cvt.rna.tf32.f32 %0, %1;" : "=r"(o) : "f"(v));
    return __uint_as_float(o);
}
__device__ __forceinline__ void cp16(uint32_t dst, const void* src) {
    asm volatile("cp.async.cg.shared.global [%0], [%1], 16;" :: "r"(dst), "l"(src) : "memory");
}
__device__ __forceinline__ void cp16z(uint32_t dst, const void* src, int bytes) {
    asm volatile("cp.async.cg.shared.global [%0], [%1], 16, %2;"
                 :: "r"(dst), "l"(src), "r"(bytes) : "memory");
}
__device__ __forceinline__ void cp_commit() {
    asm volatile("cp.async.commit_group;" ::: "memory");
}
#define CP_WAIT(n) asm volatile("cp.async.wait_group %0;" :: "n"(n) : "memory")

#define MMA_TF32(acc, af, bf)                                              \
    asm volatile(                                                          \
        "mma.sync.aligned.m16n8k8.row.col.f32.tf32.tf32.f32 "              \
        "{%0,%1,%2,%3}, {%4,%5,%6,%7}, {%8,%9}, {%0,%1,%2,%3};"            \
        : "+f"((acc)[0]), "+f"((acc)[1]), "+f"((acc)[2]), "+f"((acc)[3])   \
        : "r"((af)[0]), "r"((af)[1]), "r"((af)[2]), "r"((af)[3]),          \
          "r"((bf)[0]), "r"((bf)[1]))

// ---------------------------------------------------------------------------
// k1: fold a: w1 = lin_w^T a1, c1 = lin_b.a1 (and 2)
// ---------------------------------------------------------------------------
__global__ void k1_prep(const float* __restrict__ lin_w,
                        const float* __restrict__ lin_b,
                        const float* __restrict__ a) {
    int f = threadIdx.x;
    __shared__ float sa1[E], sa2[E], red1[E], red2[E];
    float a1v = a[f], a2v = a[E + f];
    sa1[f] = a1v;
    sa2[f] = a2v;
    __syncthreads();
    float acc1 = 0.f, acc2 = 0.f;
#pragma unroll 8
    for (int e = 0; e < E; e++) {
        float lw = lin_w[e * F + f];
        acc1 += lw * sa1[e];
        acc2 += lw * sa2[e];
    }
    g_w1[f] = acc1;
    g_w2[f] = acc2;
    float lb = lin_b[f];
    red1[f] = lb * a1v;
    red2[f] = lb * a2v;
    __syncthreads();
    for (int s = 64; s > 0; s >>= 1) {
        if (f < s) {
            red1[f] += red1[f + s];
            red2[f] += red2[f + s];
        }
        __syncthreads();
    }
    if (f == 0) {
        g_c[0] = red1[0];
        g_c[1] = red2[0];
    }
}

// ---------------------------------------------------------------------------
// k2: s1/s2 row scores. One warp per row.
// ---------------------------------------------------------------------------
__global__ void k2_scores(const float* __restrict__ x) {
    int row = (blockIdx.x * blockDim.x + threadIdx.x) >> 5;
    int lane = threadIdx.x & 31;
    if (row >= B * K) return;
    float4 xv = ((const float4*)(x + (size_t)row * F))[lane];
    float4 w1 = ((const float4*)g_w1)[lane];
    float4 w2 = ((const float4*)g_w2)[lane];
    float d1 = xv.x * w1.x + xv.y * w1.y + xv.z * w1.z + xv.w * w1.w;
    float d2 = xv.x * w2.x + xv.y * w2.y + xv.z * w2.z + xv.w * w2.w;
#pragma unroll
    for (int off = 16; off; off >>= 1) {
        d1 += __shfl_xor_sync(~0u, d1, off);
        d2 += __shfl_xor_sync(~0u, d2, off);
    }
    if (lane == 0) {
        g_s1[row] = d1 + g_c[0];
        g_s2[row] = d2 + g_c[1];
    }
}

// ---------------------------------------------------------------------------
// k2r: pre-round an fp32 array to tf32 (rna) bit patterns.
// ---------------------------------------------------------------------------
__global__ void k2r_round(const float* __restrict__ src, float* __restrict__ dst, int n4) {
    int i = blockIdx.x * 256 + threadIdx.x;
    if (i >= n4) return;
    float4 v = ((const float4*)src)[i];
    v.x = f2tf32f(v.x);
    v.y = f2tf32f(v.y);
    v.z = f2tf32f(v.z);
    v.w = f2tf32f(v.w);
    ((float4*)dst)[i] = v;
}

// ---------------------------------------------------------------------------
// k3f: fused softmax + (h = P @ x + x). One block per (b, 128 i-rows).
// Pass 1: row exp-sums (no max subtraction; |e| < ~8 by construction).
// Pass 2: per 32-j chunk: recompute e -> p = exp(e)*inv; write exact fp32
//         attn; store tf32-rna p into smem A-tile; MMA vs pre-rounded x.
// ---------------------------------------------------------------------------
__global__ void __launch_bounds__(256, 2) k3f(const float* __restrict__ x,
                                              const float* __restrict__ bias,
                                              float* __restrict__ attn) {
    extern __shared__ char sm[];
    const uint32_t sbase = smem_u32(sm);
    float* s2s = (float*)(sm + OFF_S2);
    float* s1s = (float*)(sm + OFF_S1);
    float* invs = (float*)(sm + OFF_INV);

    const int tid = threadIdx.x;
    const int wid = tid >> 5, lane = tid & 31;
    const int b = blockIdx.y;
    const int i0 = blockIdx.x * 128;
    const int warp_m = (wid >> 2) * 64;
    const int warp_n = (wid & 3) * 32;
    const int qr = lane >> 2, qc = lane & 3;

    const float* Xb = x + (size_t)b * K * F;
    const float* Xr = g_xr + (size_t)b * K * F;

    // load s2 (full row) and s1 (this tile) into smem
    for (int j = tid; j < K; j += 256) s2s[j] = g_s2[b * K + j];
    if (tid < 128) s1s[tid] = g_s1[b * K + i0 + tid];
    __syncthreads();

    // ---- Pass 1: row sums of exp ----
    {
        const float4* s2s4 = (const float4*)s2s;
#pragma unroll 1
        for (int r = 0; r < 16; r++) {
            int row = wid * 16 + r;
            float s1 = s1s[row];
            const float4* brow = (const float4*)(bias + (size_t)(i0 + row) * K);
            float sum = 0.f;
#pragma unroll
            for (int t = 0; t < 8; t++) {
                int j4 = lane + t * 32;
                float4 bv = brow[j4];
                float4 s2v = s2s4[j4];
                float v0 = s1 + s2v.x; v0 = (v0 > 0.f ? v0 : ALPHA * v0) + bv.x;
                float v1 = s1 + s2v.y; v1 = (v1 > 0.f ? v1 : ALPHA * v1) + bv.y;
                float v2 = s1 + s2v.z; v2 = (v2 > 0.f ? v2 : ALPHA * v2) + bv.z;
                float v3 = s1 + s2v.w; v3 = (v3 > 0.f ? v3 : ALPHA * v3) + bv.w;
                sum += __expf(v0) + __expf(v1) + __expf(v2) + __expf(v3);
            }
#pragma unroll
            for (int off = 16; off; off >>= 1) sum += __shfl_xor_sync(~0u, sum, off);
            if (lane == 0) invs[row] = 1.0f / sum;
        }
    }
    __syncthreads();

    // ---- Pass 2: chunked P compute + MMA ----
    const int prow = tid >> 1;            // 0..127
    const int pj16 = (tid & 1) * 16;      // 0 or 16
    const int j32 = tid >> 5, f32 = tid & 31;  // X staging

    float acc[4][4][4];
#pragma unroll
    for (int mt = 0; mt < 4; mt++)
#pragma unroll
        for (int nt = 0; nt < 4; nt++)
#pragma unroll
            for (int q = 0; q < 4; q++) acc[mt][nt][q] = 0.f;

#define COMPUTE_P(c, bi)                                                            \
    do {                                                                            \
        float s1 = s1s[prow];                                                       \
        float iv = invs[prow];                                                      \
        const float* brow = bias + (size_t)(i0 + prow) * K + (c) * 32 + pj16;       \
        float* arow = attn + ((size_t)(b * K + i0 + prow)) * K + (c) * 32 + pj16;   \
        float* pd = (float*)(sm + OFF_P + (bi) * PBUF) + prow * PPITCHF + pj16;     \
        const float* s2p = s2s + (c) * 32 + pj16;                                   \
        _Pragma("unroll") for (int q = 0; q < 4; q++) {                             \
            float4 bv = *(const float4*)(brow + q * 4);                             \
            float4 s2v = *(const float4*)(s2p + q * 4);                             \
            float4 p;                                                               \
            float v;                                                                \
            v = s1 + s2v.x; v = (v > 0.f ? v : ALPHA * v) + bv.x; p.x = __expf(v) * iv; \
            v = s1 + s2v.y; v = (v > 0.f ? v : ALPHA * v) + bv.y; p.y = __expf(v) * iv; \
            v = s1 + s2v.z; v = (v > 0.f ? v : ALPHA * v) + bv.z; p.z = __expf(v) * iv; \
            v = s1 + s2v.w; v = (v > 0.f ? v : ALPHA * v) + bv.w; p.w = __expf(v) * iv; \
            *(float4*)(arow + q * 4) = p;                                           \
            float4 pt;                                                              \
            pt.x = f2tf32f(p.x); pt.y = f2tf32f(p.y);                               \
            pt.z = f2tf32f(p.z); pt.w = f2tf32f(p.w);                               \
            *(float4*)(pd + q * 4) = pt;                                            \
        }                                                                           \
    } while (0)

#define STAGE_X(c, bi)                                                              \
    do {                                                                            \
        uint32_t xd = sbase + OFF_X + (bi) * XBUF;                                  \
        _Pragma("unroll") for (int t = 0; t < 4; t++) {                             \
            int jj = j32 + t * 8;                                                   \
            cp16(xd + jj * 544 + f32 * 16, Xr + (size_t)((c) * 32 + jj) * F + f32 * 4); \
        }                                                                           \
        cp_commit();                                                                \
    } while (0)

    STAGE_X(0, 0);
    COMPUTE_P(0, 0);
    for (int c = 0; c < 32; c++) {
        int bi = c & 1;
        if (c + 1 < 32) {
            STAGE_X(c + 1, bi ^ 1);
            COMPUTE_P(c + 1, bi ^ 1);
            CP_WAIT(1);
        } else {
            CP_WAIT(0);
        }
        __syncthreads();
        const uint32_t* Ps = (const uint32_t*)(sm + OFF_P + bi * PBUF);
        const uint32_t* Xs = (const uint32_t*)(sm + OFF_X + bi * XBUF);
#pragma unroll
        for (int kk = 0; kk < 4; kk++) {
            uint32_t af[4][4];
#pragma unroll
            for (int mt = 0; mt < 4; mt++) {
                const uint32_t* base = Ps + (warp_m + mt * 16 + qr) * PPITCHF + kk * 8 + qc;
                af[mt][0] = base[0];
                af[mt][1] = base[8 * PPITCHF];
                af[mt][2] = base[4];
                af[mt][3] = base[8 * PPITCHF + 4];
            }
            uint32_t bf[4][2];
#pragma unroll
            for (int nt = 0; nt < 4; nt++) {
                const uint32_t* base = Xs + (kk * 8 + qc) * XPITCHF + warp_n + nt * 8 + qr;
                bf[nt][0] = base[0];
                bf[nt][1] = base[4 * XPITCHF];
            }
#pragma unroll
            for (int mt = 0; mt < 4; mt++)
#pragma unroll
                for (int nt = 0; nt < 4; nt++) MMA_TF32(acc[mt][nt], af[mt], bf[nt]);
        }
        __syncthreads();
    }

    // epilogue: h = acc + x (exact x), stored tf32-rounded for k4
#pragma unroll
    for (int mt = 0; mt < 4; mt++) {
        int r0 = i0 + warp_m + mt * 16 + qr;
#pragma unroll
        for (int nt = 0; nt < 4; nt++) {
            int fc = warp_n + nt * 8 + qc * 2;
            float2 xv0 = *(const float2*)(Xb + (size_t)r0 * F + fc);
            float2 xv1 = *(const float2*)(Xb + (size_t)(r0 + 8) * F + fc);
            float2 o0 = {f2tf32f(acc[mt][nt][0] + xv0.x), f2tf32f(acc[mt][nt][1] + xv0.y)};
            float2 o1 = {f2tf32f(acc[mt][nt][2] + xv1.x), f2tf32f(acc[mt][nt][3] + xv1.y)};
            *(float2*)(g_h + ((size_t)b * K + r0) * F + fc) = o0;
            *(float2*)(g_h + ((size_t)b * K + r0 + 8) * F + fc) = o1;
        }
    }
}

// ---------------------------------------------------------------------------
// k4: h2 partial via tensor mma. A = g_wr [o x k], B = g_h [k x f].
// ---------------------------------------------------------------------------
__global__ void __launch_bounds__(256, 2) k4_lin2() {
    extern __shared__ char sm[];
    const uint32_t sbase = smem_u32(sm);
    const int tid = threadIdx.x;
    const int wid = tid >> 5, lane = tid & 31;
    const int b = blockIdx.x;
    const int ks = blockIdx.y;
    const int k0 = ks * (K / NSPLIT);
    const int warp_m = (wid >> 2) * 64;
    const int warp_n = (wid & 3) * 32;
    const int qr = lane >> 2, qc = lane & 3;

    const float* Hb = g_h + (size_t)b * K * F;
    const int r8 = tid >> 3, c8 = tid & 7;
    const int j32 = tid >> 5, f32 = tid & 31;

    float acc[4][4][4];
#pragma unroll
    for (int mt = 0; mt < 4; mt++)
#pragma unroll
        for (int nt = 0; nt < 4; nt++)
#pragma unroll
            for (int q = 0; q < 4; q++) acc[mt][nt][q] = 0.f;

#define STAGE4(c, bi)                                                                 \
    do {                                                                              \
        uint32_t ad = sbase + (bi) * PBUF;                                            \
        uint32_t bd = sbase + 2 * PBUF + (bi) * XBUF;                                 \
        _Pragma("unroll") for (int t = 0; t < 4; t++) {                               \
            int row = r8 + t * 32;                                                    \
            int vb = row < OUT2 ? 16 : 0;                                             \
            cp16z(ad + row * 144 + c8 * 16,                                           \
                  g_wr + (size_t)(row < OUT2 ? row : 0) * K + k0 + (c) * 32 + c8 * 4, \
                  vb);                                                                \
        }                                                                             \
        _Pragma("unroll") for (int t = 0; t < 4; t++) {                               \
            int jj = j32 + t * 8;                                                     \
            cp16(bd + jj * 544 + f32 * 16,                                            \
                 Hb + (size_t)(k0 + (c) * 32 + jj) * F + f32 * 4);                    \
        }                                                                             \
        cp_commit();                                                                  \
    } while (0)

    const int NCH4 = (K / NSPLIT) / 32;  // 8
    STAGE4(0, 0);
    for (int c = 0; c < NCH4; c++) {
        int bi = c & 1;
        if (c + 1 < NCH4) {
            STAGE4(c + 1, bi ^ 1);
            CP_WAIT(1);
        } else {
            CP_WAIT(0);
        }
        __syncthreads();
        const uint32_t* As = (const uint32_t*)(sm + bi * PBUF);
        const uint32_t* Bs = (const uint32_t*)(sm + 2 * PBUF + bi * XBUF);
#pragma unroll
        for (int kk = 0; kk < 4; kk++) {
            uint32_t af[4][4];
#pragma unroll
            for (int mt = 0; mt < 4; mt++) {
                const uint32_t* base = As + (warp_m + mt * 16 + qr) * PPITCHF + kk * 8 + qc;
                af[mt][0] = base[0];
                af[mt][1] = base[8 * PPITCHF];
                af[mt][2] = base[4];
                af[mt][3] = base[8 * PPITCHF + 4];
            }
            uint32_t bf[4][2];
#pragma unroll
            for (int nt = 0; nt < 4; nt++) {
                const uint32_t* base = Bs + (kk * 8 + qc) * XPITCHF + warp_n + nt * 8 + qr;
                bf[nt][0] = base[0];
                bf[nt][1] = base[4 * XPITCHF];
            }
#pragma unroll
            for (int mt = 0; mt < 4; mt++)
#pragma unroll
                for (int nt = 0; nt < 4; nt++) MMA_TF32(acc[mt][nt], af[mt], bf[nt]);
        }
        __syncthreads();
    }

    float* out = g_h2p[ks] + (size_t)b * F * OUT2;
#pragma unroll
    for (int mt = 0; mt < 4; mt++) {
        int o0 = warp_m + mt * 16 + qr;
#pragma unroll
        for (int nt = 0; nt < 4; nt++) {
            int fc = warp_n + nt * 8 + qc * 2;
            if (o0 < OUT2) {
                out[(size_t)fc * OUT2 + o0] = acc[mt][nt][0];
                out[(size_t)(fc + 1) * OUT2 + o0] = acc[mt][nt][1];
            }
            if (o0 + 8 < OUT2) {
                out[(size_t)fc * OUT2 + o0 + 8] = acc[mt][nt][2];
                out[(size_t)(fc + 1) * OUT2 + o0 + 8] = acc[mt][nt][3];
            }
        }
    }
}

// ---------------------------------------------------------------------------
// k5: out = relu(sum partials + lin2_b)
// ---------------------------------------------------------------------------
__global__ void k5_out(const float* __restrict__ lin2_b, float* __restrict__ out) {
    int i = blockIdx.x * 256 + threadIdx.x;
    if (i >= B * F * OUT2) return;
    float v = lin2_b[i % OUT2];
#pragma unroll
    for (int p = 0; p < NSPLIT; p++) v += g_h2p[p][i];
    out[i] = v > 0.f ? v : 0.f;
}

// ---------------------------------------------------------------------------
extern "C" void kernel_launch(void* const* d_in, const int* in_sizes, int n_in,
                              void* d_out, int out_size) {
    const float* x      = (const float*)d_in[0];
    const float* lin_w  = (const float*)d_in[1];
    const float* lin_b  = (const float*)d_in[2];
    const float* a      = (const float*)d_in[3];
    const float* bias   = (const float*)d_in[4];
    const float* lin2_w = (const float*)d_in[5];
    const float* lin2_b = (const float*)d_in[6];
    float* out = (float*)d_out;
    float* out_h2 = out;                           // (B,F,OUT2)
    float* out_attn = out + (size_t)B * F * OUT2;  // (B,K,K)

    cudaFuncSetAttribute(k3f, cudaFuncAttributeMaxDynamicSharedMemorySize, SMEM_K3F);
    cudaFuncSetAttribute(k4_lin2, cudaFuncAttributeMaxDynamicSharedMemorySize, SMEM_K4);

    void* xr = nullptr;
    void* wr = nullptr;
    cudaGetSymbolAddress(&xr, g_xr);
    cudaGetSymbolAddress(&wr, g_wr);

    k1_prep<<<1, 128>>>(lin_w, lin_b, a);
    k2_scores<<<(B * K) / 8, 256>>>(x);
    k2r_round<<<(B * K * F / 4 + 255) / 256, 256>>>(x, (float*)xr, B * K * F / 4);
    k2r_round<<<(OUT2 * K / 4 + 255) / 256, 256>>>(lin2_w, (float*)wr, OUT2 * K / 4);
    k3f<<<dim3(K / 128, B), 256, SMEM_K3F>>>(x, bias, out_attn);
    k4_lin2<<<dim3(B, NSPLIT), 256, SMEM_K4>>>();
    k5_out<<<(B * F * OUT2 + 255) / 256, 256>>>(lin2_b, out_h2);
}